// round 3
// baseline (speedup 1.0000x reference)
#include <cuda_runtime.h>
#include <cuda_bf16.h>
#include <mma.h>
#include <math.h>

using namespace nvcuda;
typedef __nv_bfloat16 bf16;

#define NB   32
#define SQ   1024
#define HID  1024
#define ATT  512
#define TOK  (NB*SQ)          /* 32768 */
#define QKVW 3072

// ---------------- static device scratch (no cudaMalloc allowed) ----------------
__device__ bf16  g_comb [(size_t)TOK*HID];
__device__ bf16  g_Wproj[(size_t)HID*HID];
__device__ bf16  g_Wqkv [(size_t)HID*QKVW];
__device__ bf16  g_W0   [(size_t)HID*HID];
__device__ float g_x    [(size_t)TOK*HID];
__device__ bf16  g_xb   [(size_t)TOK*HID];
__device__ float g_qkv  [(size_t)TOK*QKVW];
__device__ bf16  g_qkvb [(size_t)TOK*QKVW];
__device__ float g_s    [(size_t)NB*SQ*SQ];
__device__ bf16  g_p    [(size_t)NB*SQ*SQ];
__device__ float g_z    [(size_t)TOK*HID];
__device__ bf16  g_zb   [(size_t)TOK*HID];
__device__ float g_h    [(size_t)TOK*HID];

// ---------------- generic bf16 GEMM: C(f32) = A x B, NN or NT -----------------
// 128x128 tile, BK=32, 256 threads (8 warps as 4x2), each warp 32x64 via wmma.
template<bool BT>
__global__ void __launch_bounds__(256) gemm_bf16(
    const bf16* __restrict__ A, const bf16* __restrict__ B, float* __restrict__ C,
    int M, int N, int K, int lda, int ldb, int ldc,
    size_t sA, size_t sB, size_t sC)
{
    __shared__ __align__(32) bf16 As[128*40];
    __shared__ __align__(32) bf16 Bs[128*40];

    A += (size_t)blockIdx.z * sA;
    B += (size_t)blockIdx.z * sB;
    C += (size_t)blockIdx.z * sC;

    const int row0 = blockIdx.y * 128;
    const int n0   = blockIdx.x * 128;
    const int tid  = threadIdx.x;
    const int warp = tid >> 5;
    const int wm   = warp & 3;      // 0..3 along M (32 rows each)
    const int wn   = warp >> 2;     // 0..1 along N (64 cols each)

    wmma::fragment<wmma::accumulator,16,16,16,float> acc[2][4];
    #pragma unroll
    for (int i = 0; i < 2; i++)
        #pragma unroll
        for (int j = 0; j < 4; j++)
            wmma::fill_fragment(acc[i][j], 0.0f);

    for (int k0 = 0; k0 < K; k0 += 32) {
        // ---- A tile: 128 rows x 32 cols ----
        #pragma unroll
        for (int i = 0; i < 2; i++) {
            int u = tid + i*256;
            int r = u >> 2, c = (u & 3) * 8;
            *(uint4*)&As[r*40 + c] =
                *(const uint4*)&A[(size_t)(row0 + r)*lda + k0 + c];
        }
        // ---- B tile ----
        if (BT) {
            // B row-major [N,K]; tile 128 rows x 32 cols (same shape as A)
            #pragma unroll
            for (int i = 0; i < 2; i++) {
                int u = tid + i*256;
                int r = u >> 2, c = (u & 3) * 8;
                *(uint4*)&Bs[r*40 + c] =
                    *(const uint4*)&B[(size_t)(n0 + r)*ldb + k0 + c];
            }
        } else {
            // B row-major [K,N]; tile 32 rows x 128 cols
            #pragma unroll
            for (int i = 0; i < 2; i++) {
                int u = tid + i*256;
                int r = u >> 4, c = (u & 15) * 8;
                *(uint4*)&Bs[r*136 + c] =
                    *(const uint4*)&B[(size_t)(k0 + r)*ldb + n0 + c];
            }
        }
        __syncthreads();

        #pragma unroll
        for (int kk = 0; kk < 32; kk += 16) {
            wmma::fragment<wmma::matrix_a,16,16,16,bf16,wmma::row_major> af[2];
            #pragma unroll
            for (int i = 0; i < 2; i++)
                wmma::load_matrix_sync(af[i], &As[(wm*32 + i*16)*40 + kk], 40);

            if (BT) {
                #pragma unroll
                for (int j = 0; j < 4; j++) {
                    wmma::fragment<wmma::matrix_b,16,16,16,bf16,wmma::col_major> bfg;
                    wmma::load_matrix_sync(bfg, &Bs[(wn*64 + j*16)*40 + kk], 40);
                    #pragma unroll
                    for (int i = 0; i < 2; i++)
                        wmma::mma_sync(acc[i][j], af[i], bfg, acc[i][j]);
                }
            } else {
                #pragma unroll
                for (int j = 0; j < 4; j++) {
                    wmma::fragment<wmma::matrix_b,16,16,16,bf16,wmma::row_major> bfg;
                    wmma::load_matrix_sync(bfg, &Bs[kk*136 + wn*64 + j*16], 136);
                    #pragma unroll
                    for (int i = 0; i < 2; i++)
                        wmma::mma_sync(acc[i][j], af[i], bfg, acc[i][j]);
                }
            }
        }
        __syncthreads();
    }

    #pragma unroll
    for (int i = 0; i < 2; i++)
        #pragma unroll
        for (int j = 0; j < 4; j++)
            wmma::store_matrix_sync(
                &C[(size_t)(row0 + wm*32 + i*16)*ldc + n0 + wn*64 + j*16],
                acc[i][j], ldc, wmma::mem_row_major);
}

// ---------------- embedding: cate gathers + cont @ Wc -> comb (bf16) ----------
__global__ void embed_kernel(const int* __restrict__ cate,
                             const float* __restrict__ cont,
                             const float* __restrict__ E0,
                             const float* __restrict__ E1,
                             const float* __restrict__ E2,
                             const float* __restrict__ E3,
                             const float* __restrict__ Wc)
{
    int idx = blockIdx.x * blockDim.x + threadIdx.x;
    if (idx >= TOK * HID) return;
    int tok = idx >> 10;
    int col = idx & 1023;
    float v;
    if (col < 512) {
        int f = col >> 7, e = col & 127;
        const float* E = (f == 0) ? E0 : (f == 1) ? E1 : (f == 2) ? E2 : E3;
        int id = cate[tok*4 + f];
        v = E[(size_t)id*128 + e];
    } else {
        int j = col - 512;
        v = cont[tok*4+0]*Wc[j]      + cont[tok*4+1]*Wc[512+j]
          + cont[tok*4+2]*Wc[1024+j] + cont[tok*4+3]*Wc[1536+j];
    }
    g_comb[idx] = __float2bfloat16(v);
}

// ---------------- pack WQ1|WK1|WV1|WQ2|WK2|WV2 -> bf16 [1024,3072] ------------
__global__ void pack_qkv_kernel(const float* __restrict__ q1, const float* __restrict__ k1,
                                const float* __restrict__ v1, const float* __restrict__ q2,
                                const float* __restrict__ k2, const float* __restrict__ v2)
{
    int idx = blockIdx.x * blockDim.x + threadIdx.x;
    if (idx >= HID * QKVW) return;
    int h = idx / QKVW, j = idx % QKVW;
    int sel = j >> 9, jj = j & 511;
    const float* srcs[6] = {q1, k1, v1, q2, k2, v2};
    g_Wqkv[idx] = __float2bfloat16(srcs[sel][h*512 + jj]);
}

// ---------------- generic f32 -> bf16 convert ---------------------------------
__global__ void convert_kernel(const float* __restrict__ in, bf16* __restrict__ out, size_t n)
{
    size_t i = (size_t)blockIdx.x * blockDim.x + threadIdx.x;
    size_t stride = (size_t)gridDim.x * blockDim.x;
    for (; i < n; i += stride) out[i] = __float2bfloat16(in[i]);
}

// ---------------- x(f32) + sinusoidal PE -> xb(bf16) --------------------------
__global__ void convert_pe_kernel()
{
    size_t i = (size_t)blockIdx.x * blockDim.x + threadIdx.x;
    size_t stride = (size_t)gridDim.x * blockDim.x;
    const float c = 0.017988946039016305f;   // ln(10000)*2/1024
    for (; i < (size_t)TOK * HID; i += stride) {
        int row = (int)(i >> 10);
        int col = (int)(i & 1023);
        int s   = row & 1023;
        int ii  = col >> 1;
        float freq = expf(-c * (float)ii);
        float ang  = (float)s * freq;
        float pe   = (col & 1) ? cosf(ang) : sinf(ang);
        g_xb[i] = __float2bfloat16(g_x[i] + pe);
    }
}

// ---------------- softmax over QUERY axis (axis=1), emit bf16 probs -----------
// For each (batch, k): p[q,k] = exp(s[q,k]*scale - m_k) / sum_q(...)
__global__ void softmax_kernel(const float* __restrict__ S, bf16* __restrict__ P)
{
    int k = blockIdx.x * blockDim.x + threadIdx.x;   // column index 0..1023
    const float* s = S + (size_t)blockIdx.y * SQ * SQ + k;
    bf16*        p = P + (size_t)blockIdx.y * SQ * SQ + k;
    const float scale = 0.04419417382415922f;        // 1/sqrt(512)
    float m = -1e30f, l = 0.0f;
    for (int q = 0; q < SQ; q++) {
        float v = s[(size_t)q * SQ] * scale;
        if (v > m) { l = l * __expf(m - v); m = v; }
        l += __expf(v - m);
    }
    float inv = 1.0f / l;
    for (int q = 0; q < SQ; q++) {
        float v = s[(size_t)q * SQ] * scale;
        p[(size_t)q * SQ] = __float2bfloat16(__expf(v - m) * inv);
    }
}

// ---------------- final: out = sigmoid(h @ Wf), one warp per row --------------
__global__ void final_kernel(const float* __restrict__ Wf, float* __restrict__ out)
{
    int gid  = blockIdx.x * blockDim.x + threadIdx.x;
    int row  = gid >> 5;
    int lane = gid & 31;
    if (row >= TOK) return;
    const float* h = g_h + (size_t)row * HID;
    float acc = 0.0f;
    for (int j = lane; j < HID; j += 32) acc += h[j] * Wf[j];
    #pragma unroll
    for (int o = 16; o; o >>= 1) acc += __shfl_xor_sync(0xffffffffu, acc, o);
    if (lane == 0) out[row] = 1.0f / (1.0f + __expf(-acc));
}

// ==============================================================================
extern "C" void kernel_launch(void* const* d_in, const int* in_sizes, int n_in,
                              void* d_out, int out_size)
{
    const int*   cate  = (const int*)  d_in[0];
    const float* cont  = (const float*)d_in[1];
    // d_in[2] mask, d_in[3] targets: unused by reference
    const float* E0    = (const float*)d_in[4];
    const float* E1    = (const float*)d_in[5];
    const float* E2    = (const float*)d_in[6];
    const float* E3    = (const float*)d_in[7];
    const float* Wc    = (const float*)d_in[8];
    const float* Wproj = (const float*)d_in[9];
    const float* WQ1   = (const float*)d_in[10];
    const float* WK1   = (const float*)d_in[11];
    const float* WV1   = (const float*)d_in[12];
    const float* WQ2   = (const float*)d_in[13];
    const float* WK2   = (const float*)d_in[14];
    const float* WV2   = (const float*)d_in[15];
    const float* W0    = (const float*)d_in[16];
    const float* Wf    = (const float*)d_in[17];
    float* out = (float*)d_out;

    bf16 *comb, *Wp, *Wqkv, *W0b, *xb, *qkvb, *p, *zb;
    float *x, *qkv, *s, *z, *hb;
    cudaGetSymbolAddress((void**)&comb, g_comb);
    cudaGetSymbolAddress((void**)&Wp,   g_Wproj);
    cudaGetSymbolAddress((void**)&Wqkv, g_Wqkv);
    cudaGetSymbolAddress((void**)&W0b,  g_W0);
    cudaGetSymbolAddress((void**)&x,    g_x);
    cudaGetSymbolAddress((void**)&xb,   g_xb);
    cudaGetSymbolAddress((void**)&qkv,  g_qkv);
    cudaGetSymbolAddress((void**)&qkvb, g_qkvb);
    cudaGetSymbolAddress((void**)&s,    g_s);
    cudaGetSymbolAddress((void**)&p,    g_p);
    cudaGetSymbolAddress((void**)&z,    g_z);
    cudaGetSymbolAddress((void**)&zb,   g_zb);
    cudaGetSymbolAddress((void**)&hb,   g_h);

    // ---- weight prep ----
    convert_kernel<<<2048, 256>>>(Wproj, Wp,  (size_t)HID*HID);
    convert_kernel<<<2048, 256>>>(W0,    W0b, (size_t)HID*HID);
    pack_qkv_kernel<<<(HID*QKVW + 255)/256, 256>>>(WQ1, WK1, WV1, WQ2, WK2, WV2);

    // ---- embedding -> comb ----
    embed_kernel<<<(TOK*HID + 255)/256, 256>>>(cate, cont, E0, E1, E2, E3, Wc);

    // ---- x = comb @ Wproj ; += PE ----
    gemm_bf16<false><<<dim3(HID/128, TOK/128, 1), 256>>>(
        comb, Wp, x, TOK, HID, HID, HID, HID, HID, 0, 0, 0);
    convert_pe_kernel<<<4096, 256>>>();

    // ---- QKV = x @ [WQ1|WK1|WV1|WQ2|WK2|WV2] ----
    gemm_bf16<false><<<dim3(QKVW/128, TOK/128, 1), 256>>>(
        xb, Wqkv, qkv, TOK, QKVW, HID, HID, QKVW, QKVW, 0, 0, 0);
    convert_kernel<<<4096, 256>>>(qkv, qkvb, (size_t)TOK*QKVW);

    // ---- two attention heads ----
    for (int h = 0; h < 2; h++) {
        const bf16* Qh = qkvb + h*1536;
        const bf16* Kh = qkvb + h*1536 + 512;
        const bf16* Vh = qkvb + h*1536 + 1024;
        // scores[b] = Q K^T  (NT), per batch
        gemm_bf16<true><<<dim3(SQ/128, SQ/128, NB), 256>>>(
            Qh, Kh, s, SQ, SQ, ATT, QKVW, QKVW, SQ,
            (size_t)SQ*QKVW, (size_t)SQ*QKVW, (size_t)SQ*SQ);
        // column softmax (axis = query)
        softmax_kernel<<<dim3(SQ/256, NB), 256>>>(s, p);
        // z_h[b] = P V (NN), written into z columns [h*512, h*512+512)
        gemm_bf16<false><<<dim3(ATT/128, SQ/128, NB), 256>>>(
            p, Vh, z + h*512, SQ, ATT, SQ, SQ, QKVW, HID,
            (size_t)SQ*SQ, (size_t)SQ*QKVW, (size_t)SQ*HID);
    }

    // ---- h = z @ W0 ----
    convert_kernel<<<4096, 256>>>(z, zb, (size_t)TOK*HID);
    gemm_bf16<false><<<dim3(HID/128, TOK/128, 1), 256>>>(
        zb, W0b, hb, TOK, HID, HID, HID, HID, HID, 0, 0, 0);

    // ---- out = sigmoid(h @ Wf) ----
    final_kernel<<<(TOK*32 + 255)/256, 256>>>(Wf, out);
}

// round 14
// speedup vs baseline: 1.2576x; 1.2576x over previous
#include <cuda_runtime.h>
#include <cuda_bf16.h>
#include <mma.h>
#include <math.h>
#include <stdint.h>

using namespace nvcuda;
typedef __nv_bfloat16 bf16;

#define NB   32
#define SQ   1024
#define HID  1024
#define ATT  512
#define TOK  (NB*SQ)          /* 32768 */
#define QKVW 3072

// GEMM tiling
#define BM 128
#define BN 256
#define BK 32
#define ASTRIDE 40            /* 32 + 8 pad, elements */
#define BSTRIDE_NN 264        /* 256 + 8 pad */
#define ASTG (BM*ASTRIDE)               /* 5120 elem  */
#define BSTG_NT (BN*ASTRIDE)            /* 10240 elem */
#define BSTG_NN (BK*BSTRIDE_NN)         /* 8448 elem  */
#define SMEM_NT ((3*ASTG + 3*BSTG_NT)*2)   /* 92160 B */
#define SMEM_NN ((3*ASTG + 3*BSTG_NN)*2)   /* 81408 B */

// ---------------- static device scratch ----------------
__device__ bf16  g_comb [(size_t)TOK*HID];
__device__ bf16  g_Wproj[(size_t)HID*HID];
__device__ bf16  g_Wqkv [(size_t)HID*QKVW];
__device__ bf16  g_W0   [(size_t)HID*HID];
__device__ bf16  g_xb   [(size_t)TOK*HID];
__device__ bf16  g_qkvb [(size_t)TOK*QKVW];
__device__ float g_s    [(size_t)NB*SQ*SQ];
__device__ bf16  g_p    [(size_t)NB*SQ*SQ];
__device__ bf16  g_zb   [(size_t)TOK*HID];
__device__ bf16  g_hb   [(size_t)TOK*HID];

// ---------------- cp.async helpers (sm_80 base ISA, safe on compute_103) ------
__device__ __forceinline__ void cpa16(uint32_t s, const void* g){
    asm volatile("cp.async.cg.shared.global [%0], [%1], 16;\n" :: "r"(s), "l"(g));
}
__device__ __forceinline__ void cpa_commit(){
    asm volatile("cp.async.commit_group;\n" ::);
}
__device__ __forceinline__ uint32_t packbf(float a, float b){
    float2 f; f.x = a; f.y = b;
    __nv_bfloat162 t = __float22bfloat162_rn(f);
    return *reinterpret_cast<uint32_t*>(&t);
}

enum { EPI_BF16 = 0, EPI_PE = 1, EPI_F32 = 2 };

// ---------------- pipelined wmma GEMM: C[M,N] = A[M,K] * (BT ? B^T : B) -------
// A row-major [M,K] (lda), B row-major [N,K] if BT else [K,N] (ldb).
// Batched by blockIdx.z: A/C rows shift by bz*aYs, B rows by bz*bYs.
template<bool BT, int EPI>
__global__ void __launch_bounds__(256, 1) gemm2(
    const bf16* __restrict__ A, const bf16* __restrict__ B, void* __restrict__ Cp,
    int K, int lda, int ldb, int ldc, int aYs, int bYs)
{
    extern __shared__ bf16 sm[];
    bf16* sA = sm;
    bf16* sB = sm + 3*ASTG;
    const int BSTG = BT ? BSTG_NT : BSTG_NN;

    const int tid  = threadIdx.x;
    const int warp = tid >> 5, lane = tid & 31;
    const int n0   = blockIdx.x * BN;
    const int row0 = blockIdx.y * BM;
    const int bz   = blockIdx.z;
    const int ay   = bz*aYs + row0;
    const int by   = bz*bYs + (BT ? n0 : 0);
    const int kt   = K / BK;
    const int wm   = warp >> 2, wn = warp & 3;     // 2x4 warp grid, 64x64 each

    wmma::fragment<wmma::accumulator,16,16,16,float> acc[4][4];
    #pragma unroll
    for (int i = 0; i < 4; i++)
        #pragma unroll
        for (int j = 0; j < 4; j++)
            wmma::fill_fragment(acc[i][j], 0.0f);

    auto issue = [&](int k, int st){
        uint32_t sa = (uint32_t)__cvta_generic_to_shared(sA + st*ASTG);
        #pragma unroll
        for (int i = 0; i < 2; i++) {
            int idx = tid + i*256, r = idx >> 2, c = (idx & 3) * 8;
            cpa16(sa + (r*ASTRIDE + c)*2, A + (size_t)(ay + r)*lda + k*BK + c);
        }
        uint32_t sb = (uint32_t)__cvta_generic_to_shared(sB + st*BSTG);
        if (BT) {
            #pragma unroll
            for (int i = 0; i < 4; i++) {
                int idx = tid + i*256, r = idx >> 2, c = (idx & 3) * 8;
                cpa16(sb + (r*ASTRIDE + c)*2, B + (size_t)(by + r)*ldb + k*BK + c);
            }
        } else {
            #pragma unroll
            for (int i = 0; i < 4; i++) {
                int idx = tid + i*256, r = idx >> 5, c = (idx & 31) * 8;
                cpa16(sb + (r*BSTRIDE_NN + c)*2, B + (size_t)(by + k*BK + r)*ldb + n0 + c);
            }
        }
        cpa_commit();
    };

    issue(0, 0);
    issue(1, 1);

    for (int k = 0; k < kt; k++) {
        if (k < kt - 1) asm volatile("cp.async.wait_group 1;\n" ::);
        else            asm volatile("cp.async.wait_group 0;\n" ::);
        __syncthreads();
        if (k + 2 < kt) issue(k + 2, (k + 2) % 3);

        const bf16* a0 = sA + (k % 3)*ASTG;
        const bf16* b0 = sB + (k % 3)*BSTG;

        #pragma unroll
        for (int kk = 0; kk < BK; kk += 16) {
            wmma::fragment<wmma::matrix_a,16,16,16,bf16,wmma::row_major> af[4];
            #pragma unroll
            for (int i = 0; i < 4; i++)
                wmma::load_matrix_sync(af[i], a0 + (wm*64 + i*16)*ASTRIDE + kk, ASTRIDE);
            if (BT) {
                #pragma unroll
                for (int j = 0; j < 4; j++) {
                    wmma::fragment<wmma::matrix_b,16,16,16,bf16,wmma::col_major> bfr;
                    wmma::load_matrix_sync(bfr, b0 + (wn*64 + j*16)*ASTRIDE + kk, ASTRIDE);
                    #pragma unroll
                    for (int i = 0; i < 4; i++)
                        wmma::mma_sync(acc[i][j], af[i], bfr, acc[i][j]);
                }
            } else {
                #pragma unroll
                for (int j = 0; j < 4; j++) {
                    wmma::fragment<wmma::matrix_b,16,16,16,bf16,wmma::row_major> bfr;
                    wmma::load_matrix_sync(bfr, b0 + kk*BSTRIDE_NN + wn*64 + j*16, BSTRIDE_NN);
                    #pragma unroll
                    for (int i = 0; i < 4; i++)
                        wmma::mma_sync(acc[i][j], af[i], bfr, acc[i][j]);
                }
            }
        }
    }
    __syncthreads();   // all cp.async drained; smem reusable as epilogue scratch

    if (EPI == EPI_F32) {
        float* C = (float*)Cp;
        #pragma unroll
        for (int i = 0; i < 4; i++)
            #pragma unroll
            for (int j = 0; j < 4; j++)
                wmma::store_matrix_sync(
                    C + (size_t)(ay + wm*64 + i*16)*ldc + n0 + wn*64 + j*16,
                    acc[i][j], ldc, wmma::mem_row_major);
    } else {
        float* scr = (float*)sm + warp*336;   // 16x20 f32 per-warp scratch
        const int r = lane >> 1, hf = lane & 1;
        #pragma unroll
        for (int i = 0; i < 4; i++) {
            const int grow = ay + wm*64 + i*16 + r;
            const int srow = grow & (SQ - 1);
            #pragma unroll
            for (int j = 0; j < 4; j++) {
                wmma::store_matrix_sync(scr, acc[i][j], 20, wmma::mem_row_major);
                __syncwarp();
                const float* sp = scr + r*20 + hf*8;
                const int gcol = n0 + wn*64 + j*16 + hf*8;
                float4 v0 = reinterpret_cast<const float4*>(sp)[0];
                float4 v1 = reinterpret_cast<const float4*>(sp)[1];
                if (EPI == EPI_PE) {
                    float vv[8] = {v0.x, v0.y, v0.z, v0.w, v1.x, v1.y, v1.z, v1.w};
                    #pragma unroll
                    for (int t = 0; t < 4; t++) {
                        int ii = (gcol >> 1) + t;
                        float freq = expf(-0.017988946039016305f * (float)ii);
                        float sn, cs;
                        sincosf((float)srow * freq, &sn, &cs);
                        vv[2*t]   += sn;
                        vv[2*t+1] += cs;
                    }
                    v0.x=vv[0]; v0.y=vv[1]; v0.z=vv[2]; v0.w=vv[3];
                    v1.x=vv[4]; v1.y=vv[5]; v1.z=vv[6]; v1.w=vv[7];
                }
                uint4 u;
                u.x = packbf(v0.x, v0.y); u.y = packbf(v0.z, v0.w);
                u.z = packbf(v1.x, v1.y); u.w = packbf(v1.z, v1.w);
                *reinterpret_cast<uint4*>((bf16*)Cp + (size_t)grow*ldc + gcol) = u;
                __syncwarp();
            }
        }
    }
}

// ---------------- embedding: cate gathers + cont @ Wc -> comb (bf16) ----------
__global__ void embed_kernel(const int* __restrict__ cate,
                             const float* __restrict__ cont,
                             const float* __restrict__ E0, const float* __restrict__ E1,
                             const float* __restrict__ E2, const float* __restrict__ E3,
                             const float* __restrict__ Wc)
{
    int idx = blockIdx.x * blockDim.x + threadIdx.x;   // TOK*256 threads, 4 cols each
    int tok = idx >> 8;
    int col = (idx & 255) * 4;
    float4 v;
    if (col < 512) {
        int f = col >> 7, e = col & 127;
        const float* E = (f == 0) ? E0 : (f == 1) ? E1 : (f == 2) ? E2 : E3;
        int id = __ldg(&cate[tok*4 + f]);
        v = *reinterpret_cast<const float4*>(&E[(size_t)id * 128 + e]);
    } else {
        int j = col - 512;
        float c0 = cont[tok*4+0], c1 = cont[tok*4+1], c2 = cont[tok*4+2], c3 = cont[tok*4+3];
        float4 w0 = *reinterpret_cast<const float4*>(&Wc[j]);
        float4 w1 = *reinterpret_cast<const float4*>(&Wc[512  + j]);
        float4 w2 = *reinterpret_cast<const float4*>(&Wc[1024 + j]);
        float4 w3 = *reinterpret_cast<const float4*>(&Wc[1536 + j]);
        v.x = c0*w0.x + c1*w1.x + c2*w2.x + c3*w3.x;
        v.y = c0*w0.y + c1*w1.y + c2*w2.y + c3*w3.y;
        v.z = c0*w0.z + c1*w1.z + c2*w2.z + c3*w3.z;
        v.w = c0*w0.w + c1*w1.w + c2*w2.w + c3*w3.w;
    }
    uint2 u; u.x = packbf(v.x, v.y); u.y = packbf(v.z, v.w);
    *reinterpret_cast<uint2*>(&g_comb[(size_t)tok * HID + col]) = u;
}

// ---------------- weight prep ----------------
__global__ void convert_kernel(const float* __restrict__ in, bf16* __restrict__ out, size_t n)
{
    size_t i = (size_t)blockIdx.x * blockDim.x + threadIdx.x;
    size_t stride = (size_t)gridDim.x * blockDim.x;
    for (; i < n; i += stride) out[i] = __float2bfloat16(in[i]);
}

__global__ void pack_qkv_kernel(const float* __restrict__ q1, const float* __restrict__ k1,
                                const float* __restrict__ v1, const float* __restrict__ q2,
                                const float* __restrict__ k2, const float* __restrict__ v2)
{
    int idx = blockIdx.x * blockDim.x + threadIdx.x;
    if (idx >= HID * QKVW) return;
    int h = idx / QKVW, j = idx % QKVW;
    int sel = j >> 9, jj = j & 511;
    const float* srcs[6] = {q1, k1, v1, q2, k2, v2};
    g_Wqkv[idx] = __float2bfloat16(srcs[sel][h*512 + jj]);
}

// ---------------- softmax over QUERY axis (applies 1/sqrt(512)) ---------------
__global__ void softmax_kernel(const float* __restrict__ S, bf16* __restrict__ P)
{
    int k = blockIdx.x * blockDim.x + threadIdx.x;
    const float* s = S + (size_t)blockIdx.y * SQ * SQ + k;
    bf16*        p = P + (size_t)blockIdx.y * SQ * SQ + k;
    const float scale = 0.04419417382415922f;
    float m = -1e30f, l = 0.0f;
    for (int q = 0; q < SQ; q++) {
        float v = s[(size_t)q * SQ] * scale;
        if (v > m) { l = l * __expf(m - v); m = v; }
        l += __expf(v - m);
    }
    float inv = 1.0f / l;
    for (int q = 0; q < SQ; q++) {
        float v = s[(size_t)q * SQ] * scale;
        p[(size_t)q * SQ] = __float2bfloat16(__expf(v - m) * inv);
    }
}

// ---------------- final: out = sigmoid(h @ Wf), one warp per row --------------
__global__ void final_kernel(const float* __restrict__ Wf, float* __restrict__ out)
{
    int gid  = blockIdx.x * blockDim.x + threadIdx.x;
    int row  = gid >> 5;
    int lane = gid & 31;
    const bf16* h = g_hb + (size_t)row * HID;
    float acc = 0.0f;
    for (int j = lane; j < HID; j += 32) acc += __bfloat162float(h[j]) * Wf[j];
    #pragma unroll
    for (int o = 16; o; o >>= 1) acc += __shfl_xor_sync(0xffffffffu, acc, o);
    if (lane == 0) out[row] = 1.0f / (1.0f + __expf(-acc));
}

// ==============================================================================
extern "C" void kernel_launch(void* const* d_in, const int* in_sizes, int n_in,
                              void* d_out, int out_size)
{
    const int*   cate  = (const int*)  d_in[0];
    const float* cont  = (const float*)d_in[1];
    const float* E0    = (const float*)d_in[4];
    const float* E1    = (const float*)d_in[5];
    const float* E2    = (const float*)d_in[6];
    const float* E3    = (const float*)d_in[7];
    const float* Wc    = (const float*)d_in[8];
    const float* Wproj = (const float*)d_in[9];
    const float* WQ1   = (const float*)d_in[10];
    const float* WK1   = (const float*)d_in[11];
    const float* WV1   = (const float*)d_in[12];
    const float* WQ2   = (const float*)d_in[13];
    const float* WK2   = (const float*)d_in[14];
    const float* WV2   = (const float*)d_in[15];
    const float* W0    = (const float*)d_in[16];
    const float* Wf    = (const float*)d_in[17];
    float* out = (float*)d_out;

    bf16 *comb, *Wp, *Wqkv, *W0b, *xb, *qkvb, *p, *zb, *hb;
    float *s;
    cudaGetSymbolAddress((void**)&comb, g_comb);
    cudaGetSymbolAddress((void**)&Wp,   g_Wproj);
    cudaGetSymbolAddress((void**)&Wqkv, g_Wqkv);
    cudaGetSymbolAddress((void**)&W0b,  g_W0);
    cudaGetSymbolAddress((void**)&xb,   g_xb);
    cudaGetSymbolAddress((void**)&qkvb, g_qkvb);
    cudaGetSymbolAddress((void**)&s,    g_s);
    cudaGetSymbolAddress((void**)&p,    g_p);
    cudaGetSymbolAddress((void**)&zb,   g_zb);
    cudaGetSymbolAddress((void**)&hb,   g_hb);   // FIX: was (void*)g_hb from host
                                                 // (host shadow addr) -> W0 GEMM
                                                 // wrote garbage, g_hb stayed 0,
                                                 // output was constant sigmoid(0)

    cudaFuncSetAttribute(gemm2<false, EPI_PE>,
                         cudaFuncAttributeMaxDynamicSharedMemorySize, SMEM_NN);
    cudaFuncSetAttribute(gemm2<false, EPI_BF16>,
                         cudaFuncAttributeMaxDynamicSharedMemorySize, SMEM_NN);
    cudaFuncSetAttribute(gemm2<true,  EPI_F32>,
                         cudaFuncAttributeMaxDynamicSharedMemorySize, SMEM_NT);

    // ---- weight prep ----
    convert_kernel<<<2048, 256>>>(Wproj, Wp,  (size_t)HID*HID);
    convert_kernel<<<2048, 256>>>(W0,    W0b, (size_t)HID*HID);
    pack_qkv_kernel<<<(HID*QKVW + 255)/256, 256>>>(WQ1, WK1, WV1, WQ2, WK2, WV2);

    // ---- embedding ----
    embed_kernel<<<TOK, 256>>>(cate, cont, E0, E1, E2, E3, Wc);

    // ---- proj: xb = comb @ Wproj, + PE, bf16 out ----
    gemm2<false, EPI_PE><<<dim3(HID/BN, TOK/BM, 1), 256, SMEM_NN>>>(
        comb, Wp, xb, HID, HID, HID, HID, 0, 0);

    // ---- qkv = xb @ Wqkv, bf16 out ----
    gemm2<false, EPI_BF16><<<dim3(QKVW/BN, TOK/BM, 1), 256, SMEM_NN>>>(
        xb, Wqkv, qkvb, HID, HID, QKVW, QKVW, 0, 0);

    // ---- two attention heads ----
    for (int h = 0; h < 2; h++) {
        const bf16* Qh = qkvb + h*1536;
        const bf16* Kh = qkvb + h*1536 + 512;
        const bf16* Vh = qkvb + h*1536 + 1024;
        // scores[b] = Q K^T (NT), f32 out, unscaled (softmax applies scale)
        gemm2<true, EPI_F32><<<dim3(SQ/BN, SQ/BM, NB), 256, SMEM_NT>>>(
            Qh, Kh, s, ATT, QKVW, QKVW, SQ, SQ, SQ);
        // column softmax over query axis
        softmax_kernel<<<dim3(SQ/256, NB), 256>>>(s, p);
        // z_h[b] = P V (NN), bf16 out into zb columns [h*512, h*512+512)
        gemm2<false, EPI_BF16><<<dim3(ATT/BN, SQ/BM, NB), 256, SMEM_NN>>>(
            p, Vh, zb + h*512, SQ, SQ, QKVW, HID, SQ, SQ);
    }

    // ---- h = z @ W0, bf16 out ----
    gemm2<false, EPI_BF16><<<dim3(HID/BN, TOK/BM, 1), 256, SMEM_NN>>>(
        zb, W0b, hb, HID, HID, HID, HID, 0, 0);

    // ---- out = sigmoid(h @ Wf) ----
    final_kernel<<<TOK/8, 256>>>(Wf, out);
}

// round 15
// speedup vs baseline: 1.4519x; 1.1545x over previous
#include <cuda_runtime.h>
#include <cuda_bf16.h>
#include <mma.h>
#include <math.h>
#include <stdint.h>

using namespace nvcuda;
typedef __nv_bfloat16 bf16;

#define NB   32
#define SQ   1024
#define HID  1024
#define ATT  512
#define TOK  (NB*SQ)          /* 32768 */
#define QKVW 3072

// GEMM tiling
#define BM 128
#define BN 256
#define BK 32
#define ASTRIDE 40            /* 32 + 8 pad, elements */
#define BSTRIDE_NN 264        /* 256 + 8 pad */
#define ASTG (BM*ASTRIDE)               /* 5120 elem  */
#define BSTG_NT (BN*ASTRIDE)            /* 10240 elem */
#define BSTG_NN (BK*BSTRIDE_NN)         /* 8448 elem  */
#define SMEM_NT ((3*ASTG + 3*BSTG_NT)*2)   /* 92160 B */
#define SMEM_NN ((3*ASTG + 3*BSTG_NN)*2)   /* 81408 B */

// ---------------- static device scratch ----------------
__device__ bf16  g_comb [(size_t)TOK*HID];
__device__ bf16  g_Wproj[(size_t)HID*HID];
__device__ bf16  g_Wqkv [(size_t)HID*QKVW];
__device__ bf16  g_W0   [(size_t)HID*HID];
__device__ bf16  g_pe   [(size_t)SQ*HID];      // sinusoidal PE matrix (bf16)
__device__ bf16  g_W2   [(size_t)HID*QKVW];    // Wproj @ Wqkv
__device__ bf16  g_peqkv[(size_t)SQ*QKVW];     // PE @ Wqkv (row bias for qkv)
__device__ bf16  g_qkvb [(size_t)TOK*QKVW];
__device__ bf16  g_p    [(size_t)NB*SQ*SQ];    // bf16 scores, softmaxed in place
__device__ bf16  g_zb   [(size_t)TOK*HID];
__device__ bf16  g_hb   [(size_t)TOK*HID];

// ---------------- cp.async helpers (sm_80 base ISA, safe on compute_103) ------
__device__ __forceinline__ void cpa16(uint32_t s, const void* g){
    asm volatile("cp.async.cg.shared.global [%0], [%1], 16;\n" :: "r"(s), "l"(g));
}
__device__ __forceinline__ void cpa_commit(){
    asm volatile("cp.async.commit_group;\n" ::);
}
__device__ __forceinline__ uint32_t packbf(float a, float b){
    float2 f; f.x = a; f.y = b;
    __nv_bfloat162 t = __float22bfloat162_rn(f);
    return *reinterpret_cast<uint32_t*>(&t);
}

enum { EPI_BF16 = 0, EPI_BIAS = 1 };

// ---------------- pipelined wmma GEMM: C[M,N] = A[M,K] * (BT ? B^T : B) -------
// A row-major [M,K] (lda), B row-major [N,K] if BT else [K,N] (ldb).
// Batched by blockIdx.z: A/C rows shift by bz*aYs, B rows by bz*bYs.
// EPI_BIAS adds bias[(row & SQ-1)*ldc + col] (bf16) in the epilogue.
template<bool BT, int EPI>
__global__ void __launch_bounds__(256, 1) gemm2(
    const bf16* __restrict__ A, const bf16* __restrict__ B, void* __restrict__ Cp,
    int K, int lda, int ldb, int ldc, int aYs, int bYs,
    const bf16* __restrict__ bias)
{
    extern __shared__ bf16 sm[];
    bf16* sA = sm;
    bf16* sB = sm + 3*ASTG;
    const int BSTG = BT ? BSTG_NT : BSTG_NN;

    const int tid  = threadIdx.x;
    const int warp = tid >> 5, lane = tid & 31;
    const int n0   = blockIdx.x * BN;
    const int row0 = blockIdx.y * BM;
    const int bz   = blockIdx.z;
    const int ay   = bz*aYs + row0;
    const int by   = bz*bYs + (BT ? n0 : 0);
    const int kt   = K / BK;
    const int wm   = warp >> 2, wn = warp & 3;     // 2x4 warp grid, 64x64 each

    wmma::fragment<wmma::accumulator,16,16,16,float> acc[4][4];
    #pragma unroll
    for (int i = 0; i < 4; i++)
        #pragma unroll
        for (int j = 0; j < 4; j++)
            wmma::fill_fragment(acc[i][j], 0.0f);

    auto issue = [&](int k, int st){
        uint32_t sa = (uint32_t)__cvta_generic_to_shared(sA + st*ASTG);
        #pragma unroll
        for (int i = 0; i < 2; i++) {
            int idx = tid + i*256, r = idx >> 2, c = (idx & 3) * 8;
            cpa16(sa + (r*ASTRIDE + c)*2, A + (size_t)(ay + r)*lda + k*BK + c);
        }
        uint32_t sb = (uint32_t)__cvta_generic_to_shared(sB + st*BSTG);
        if (BT) {
            #pragma unroll
            for (int i = 0; i < 4; i++) {
                int idx = tid + i*256, r = idx >> 2, c = (idx & 3) * 8;
                cpa16(sb + (r*ASTRIDE + c)*2, B + (size_t)(by + r)*ldb + k*BK + c);
            }
        } else {
            #pragma unroll
            for (int i = 0; i < 4; i++) {
                int idx = tid + i*256, r = idx >> 5, c = (idx & 31) * 8;
                cpa16(sb + (r*BSTRIDE_NN + c)*2, B + (size_t)(by + k*BK + r)*ldb + n0 + c);
            }
        }
        cpa_commit();
    };

    issue(0, 0);
    issue(1, 1);

    for (int k = 0; k < kt; k++) {
        if (k < kt - 1) asm volatile("cp.async.wait_group 1;\n" ::);
        else            asm volatile("cp.async.wait_group 0;\n" ::);
        __syncthreads();
        if (k + 2 < kt) issue(k + 2, (k + 2) % 3);

        const bf16* a0 = sA + (k % 3)*ASTG;
        const bf16* b0 = sB + (k % 3)*BSTG;

        #pragma unroll
        for (int kk = 0; kk < BK; kk += 16) {
            wmma::fragment<wmma::matrix_a,16,16,16,bf16,wmma::row_major> af[4];
            #pragma unroll
            for (int i = 0; i < 4; i++)
                wmma::load_matrix_sync(af[i], a0 + (wm*64 + i*16)*ASTRIDE + kk, ASTRIDE);
            if (BT) {
                #pragma unroll
                for (int j = 0; j < 4; j++) {
                    wmma::fragment<wmma::matrix_b,16,16,16,bf16,wmma::col_major> bfr;
                    wmma::load_matrix_sync(bfr, b0 + (wn*64 + j*16)*ASTRIDE + kk, ASTRIDE);
                    #pragma unroll
                    for (int i = 0; i < 4; i++)
                        wmma::mma_sync(acc[i][j], af[i], bfr, acc[i][j]);
                }
            } else {
                #pragma unroll
                for (int j = 0; j < 4; j++) {
                    wmma::fragment<wmma::matrix_b,16,16,16,bf16,wmma::row_major> bfr;
                    wmma::load_matrix_sync(bfr, b0 + kk*BSTRIDE_NN + wn*64 + j*16, BSTRIDE_NN);
                    #pragma unroll
                    for (int i = 0; i < 4; i++)
                        wmma::mma_sync(acc[i][j], af[i], bfr, acc[i][j]);
                }
            }
        }
    }
    __syncthreads();   // all cp.async drained; smem reusable as epilogue scratch

    // ---- epilogue: stage frags through smem, emit bf16 (optionally + bias) ----
    float* scr = (float*)sm + warp*336;   // 16x20 f32 per-warp scratch
    const int r = lane >> 1, hf = lane & 1;
    #pragma unroll
    for (int i = 0; i < 4; i++) {
        const int grow = ay + wm*64 + i*16 + r;
        const int srow = grow & (SQ - 1);
        #pragma unroll
        for (int j = 0; j < 4; j++) {
            wmma::store_matrix_sync(scr, acc[i][j], 20, wmma::mem_row_major);
            __syncwarp();
            const float* sp = scr + r*20 + hf*8;
            const int gcol = n0 + wn*64 + j*16 + hf*8;
            float4 v0 = reinterpret_cast<const float4*>(sp)[0];
            float4 v1 = reinterpret_cast<const float4*>(sp)[1];
            if (EPI == EPI_BIAS) {
                const uint4 bv = *reinterpret_cast<const uint4*>(
                    bias + (size_t)srow*ldc + gcol);
                float2 b0 = __bfloat1622float2(*(const __nv_bfloat162*)&bv.x);
                float2 b1 = __bfloat1622float2(*(const __nv_bfloat162*)&bv.y);
                float2 b2 = __bfloat1622float2(*(const __nv_bfloat162*)&bv.z);
                float2 b3 = __bfloat1622float2(*(const __nv_bfloat162*)&bv.w);
                v0.x += b0.x; v0.y += b0.y; v0.z += b1.x; v0.w += b1.y;
                v1.x += b2.x; v1.y += b2.y; v1.z += b3.x; v1.w += b3.y;
            }
            uint4 u;
            u.x = packbf(v0.x, v0.y); u.y = packbf(v0.z, v0.w);
            u.z = packbf(v1.x, v1.y); u.w = packbf(v1.z, v1.w);
            *reinterpret_cast<uint4*>((bf16*)Cp + (size_t)grow*ldc + gcol) = u;
            __syncwarp();
        }
    }
}

// ---------------- embedding: cate gathers + cont @ Wc -> comb (bf16) ----------
__global__ void embed_kernel(const int* __restrict__ cate,
                             const float* __restrict__ cont,
                             const float* __restrict__ E0, const float* __restrict__ E1,
                             const float* __restrict__ E2, const float* __restrict__ E3,
                             const float* __restrict__ Wc)
{
    int idx = blockIdx.x * blockDim.x + threadIdx.x;   // TOK*256 threads, 4 cols each
    int tok = idx >> 8;
    int col = (idx & 255) * 4;
    float4 v;
    if (col < 512) {
        int f = col >> 7, e = col & 127;
        const float* E = (f == 0) ? E0 : (f == 1) ? E1 : (f == 2) ? E2 : E3;
        int id = __ldg(&cate[tok*4 + f]);
        v = *reinterpret_cast<const float4*>(&E[(size_t)id * 128 + e]);
    } else {
        int j = col - 512;
        float c0 = cont[tok*4+0], c1 = cont[tok*4+1], c2 = cont[tok*4+2], c3 = cont[tok*4+3];
        float4 w0 = *reinterpret_cast<const float4*>(&Wc[j]);
        float4 w1 = *reinterpret_cast<const float4*>(&Wc[512  + j]);
        float4 w2 = *reinterpret_cast<const float4*>(&Wc[1024 + j]);
        float4 w3 = *reinterpret_cast<const float4*>(&Wc[1536 + j]);
        v.x = c0*w0.x + c1*w1.x + c2*w2.x + c3*w3.x;
        v.y = c0*w0.y + c1*w1.y + c2*w2.y + c3*w3.y;
        v.z = c0*w0.z + c1*w1.z + c2*w2.z + c3*w3.z;
        v.w = c0*w0.w + c1*w1.w + c2*w2.w + c3*w3.w;
    }
    uint2 u; u.x = packbf(v.x, v.y); u.y = packbf(v.z, v.w);
    *reinterpret_cast<uint2*>(&g_comb[(size_t)tok * HID + col]) = u;
}

// ---------------- weight prep ----------------
__global__ void convert_kernel(const float* __restrict__ in, bf16* __restrict__ out, size_t n)
{
    size_t i = (size_t)blockIdx.x * blockDim.x + threadIdx.x;
    size_t stride = (size_t)gridDim.x * blockDim.x;
    for (; i < n; i += stride) out[i] = __float2bfloat16(in[i]);
}

__global__ void pack_qkv_kernel(const float* __restrict__ q1, const float* __restrict__ k1,
                                const float* __restrict__ v1, const float* __restrict__ q2,
                                const float* __restrict__ k2, const float* __restrict__ v2)
{
    int idx = blockIdx.x * blockDim.x + threadIdx.x;
    if (idx >= HID * QKVW) return;
    int h = idx / QKVW, j = idx % QKVW;
    int sel = j >> 9, jj = j & 511;
    const float* srcs[6] = {q1, k1, v1, q2, k2, v2};
    g_Wqkv[idx] = __float2bfloat16(srcs[sel][h*512 + jj]);
}

// ---------------- PE matrix: g_pe[s, 2i]=sin(s*f_i), [s,2i+1]=cos(s*f_i) ------
__global__ void gen_pe_kernel()
{
    int idx = blockIdx.x * blockDim.x + threadIdx.x;   // SQ*512 threads
    if (idx >= SQ * 512) return;
    int srow = idx >> 9;
    int ii   = idx & 511;
    float freq = expf(-0.017988946039016305f * (float)ii);  // ln(1e4)*2/1024
    float sn, cs;
    sincosf((float)srow * freq, &sn, &cs);
    *reinterpret_cast<uint32_t*>(&g_pe[(size_t)srow * HID + 2*ii]) = packbf(sn, cs);
}

// ---------------- softmax over QUERY axis, bf16 in-place (applies scale) ------
__global__ void softmax_kernel(bf16* __restrict__ P)
{
    int k = blockIdx.x * blockDim.x + threadIdx.x;
    bf16* p = P + (size_t)blockIdx.y * SQ * SQ + k;
    const float scale = 0.04419417382415922f;        // 1/sqrt(512)
    float m = -1e30f, l = 0.0f;
    for (int q = 0; q < SQ; q++) {
        float v = __bfloat162float(p[(size_t)q * SQ]) * scale;
        if (v > m) { l = l * __expf(m - v); m = v; }
        l += __expf(v - m);
    }
    float inv = 1.0f / l;
    for (int q = 0; q < SQ; q++) {
        float v = __bfloat162float(p[(size_t)q * SQ]) * scale;
        p[(size_t)q * SQ] = __float2bfloat16(__expf(v - m) * inv);
    }
}

// ---------------- final: out = sigmoid(h @ Wf), one warp per row --------------
__global__ void final_kernel(const float* __restrict__ Wf, float* __restrict__ out)
{
    int gid  = blockIdx.x * blockDim.x + threadIdx.x;
    int row  = gid >> 5;
    int lane = gid & 31;
    const bf16* h = g_hb + (size_t)row * HID;
    float acc = 0.0f;
    for (int j = lane; j < HID; j += 32) acc += __bfloat162float(h[j]) * Wf[j];
    #pragma unroll
    for (int o = 16; o; o >>= 1) acc += __shfl_xor_sync(0xffffffffu, acc, o);
    if (lane == 0) out[row] = 1.0f / (1.0f + __expf(-acc));
}

// ==============================================================================
extern "C" void kernel_launch(void* const* d_in, const int* in_sizes, int n_in,
                              void* d_out, int out_size)
{
    const int*   cate  = (const int*)  d_in[0];
    const float* cont  = (const float*)d_in[1];
    const float* E0    = (const float*)d_in[4];
    const float* E1    = (const float*)d_in[5];
    const float* E2    = (const float*)d_in[6];
    const float* E3    = (const float*)d_in[7];
    const float* Wc    = (const float*)d_in[8];
    const float* Wproj = (const float*)d_in[9];
    const float* WQ1   = (const float*)d_in[10];
    const float* WK1   = (const float*)d_in[11];
    const float* WV1   = (const float*)d_in[12];
    const float* WQ2   = (const float*)d_in[13];
    const float* WK2   = (const float*)d_in[14];
    const float* WV2   = (const float*)d_in[15];
    const float* W0    = (const float*)d_in[16];
    const float* Wf    = (const float*)d_in[17];
    float* out = (float*)d_out;

    bf16 *comb, *Wp, *Wqkv, *W0b, *pe, *W2, *peqkv, *qkvb, *p, *zb, *hb;
    cudaGetSymbolAddress((void**)&comb,  g_comb);
    cudaGetSymbolAddress((void**)&Wp,    g_Wproj);
    cudaGetSymbolAddress((void**)&Wqkv,  g_Wqkv);
    cudaGetSymbolAddress((void**)&W0b,   g_W0);
    cudaGetSymbolAddress((void**)&pe,    g_pe);
    cudaGetSymbolAddress((void**)&W2,    g_W2);
    cudaGetSymbolAddress((void**)&peqkv, g_peqkv);
    cudaGetSymbolAddress((void**)&qkvb,  g_qkvb);
    cudaGetSymbolAddress((void**)&p,     g_p);
    cudaGetSymbolAddress((void**)&zb,    g_zb);
    cudaGetSymbolAddress((void**)&hb,    g_hb);

    cudaFuncSetAttribute(gemm2<false, EPI_BF16>,
                         cudaFuncAttributeMaxDynamicSharedMemorySize, SMEM_NN);
    cudaFuncSetAttribute(gemm2<false, EPI_BIAS>,
                         cudaFuncAttributeMaxDynamicSharedMemorySize, SMEM_NN);
    cudaFuncSetAttribute(gemm2<true,  EPI_BF16>,
                         cudaFuncAttributeMaxDynamicSharedMemorySize, SMEM_NT);

    // ---- weight prep ----
    convert_kernel<<<2048, 256>>>(Wproj, Wp,  (size_t)HID*HID);
    convert_kernel<<<2048, 256>>>(W0,    W0b, (size_t)HID*HID);
    pack_qkv_kernel<<<(HID*QKVW + 255)/256, 256>>>(WQ1, WK1, WV1, WQ2, WK2, WV2);
    gen_pe_kernel<<<(SQ*512 + 255)/256, 256>>>();

    // ---- fused weights: W2 = Wproj @ Wqkv ; PEQKV = PE @ Wqkv ----
    gemm2<false, EPI_BF16><<<dim3(QKVW/BN, HID/BM, 1), 256, SMEM_NN>>>(
        Wp, Wqkv, W2, HID, HID, QKVW, QKVW, 0, 0, nullptr);
    gemm2<false, EPI_BF16><<<dim3(QKVW/BN, SQ/BM, 1), 256, SMEM_NN>>>(
        pe, Wqkv, peqkv, HID, HID, QKVW, QKVW, 0, 0, nullptr);

    // ---- embedding ----
    embed_kernel<<<TOK, 256>>>(cate, cont, E0, E1, E2, E3, Wc);

    // ---- qkv = comb @ W2 + PEQKV[row mod SQ]  (proj GEMM fused away) ----
    gemm2<false, EPI_BIAS><<<dim3(QKVW/BN, TOK/BM, 1), 256, SMEM_NN>>>(
        comb, W2, qkvb, HID, HID, QKVW, QKVW, 0, 0, peqkv);

    // ---- two attention heads ----
    for (int h = 0; h < 2; h++) {
        const bf16* Qh = qkvb + h*1536;
        const bf16* Kh = qkvb + h*1536 + 512;
        const bf16* Vh = qkvb + h*1536 + 1024;
        // scores[b] = Q K^T (NT), bf16 out (unscaled; softmax applies scale)
        gemm2<true, EPI_BF16><<<dim3(SQ/BN, SQ/BM, NB), 256, SMEM_NT>>>(
            Qh, Kh, p, ATT, QKVW, QKVW, SQ, SQ, SQ, nullptr);
        // column softmax over query axis, in place on bf16
        softmax_kernel<<<dim3(SQ/256, NB), 256>>>(p);
        // z_h[b] = P V (NN), bf16 out into zb columns [h*512, h*512+512)
        gemm2<false, EPI_BF16><<<dim3(ATT/BN, SQ/BM, NB), 256, SMEM_NN>>>(
            p, Vh, zb + h*512, SQ, SQ, QKVW, HID, SQ, SQ, nullptr);
    }

    // ---- h = z @ W0, bf16 out ----
    gemm2<false, EPI_BF16><<<dim3(HID/BN, TOK/BM, 1), 256, SMEM_NN>>>(
        zb, W0b, hb, HID, HID, HID, HID, 0, 0, nullptr);

    // ---- out = sigmoid(h @ Wf) ----
    final_kernel<<<TOK/8, 256>>>(Wf, out);
}

// round 16
// speedup vs baseline: 2.1932x; 1.5106x over previous
#include <cuda_runtime.h>
#include <cuda_bf16.h>
#include <mma.h>
#include <math.h>
#include <stdint.h>

using namespace nvcuda;
typedef __nv_bfloat16 bf16;

#define NB   32
#define SQ   1024
#define HID  1024
#define ATT  512
#define TOK  (NB*SQ)          /* 32768 */
#define QKVW 3072
#define VOC  1000
#define VOCP 1024             /* padded vocab rows */

// GEMM tiling
#define BM 128
#define BN 256
#define BK 32
#define ASTRIDE 40            /* 32 + 8 pad, elements */
#define BSTRIDE_NN 264        /* 256 + 8 pad */
#define ASTG (BM*ASTRIDE)               /* 5120 elem  */
#define BSTG_NT (BN*ASTRIDE)            /* 10240 elem */
#define BSTG_NN (BK*BSTRIDE_NN)         /* 8448 elem  */
#define SMEM_NT ((3*ASTG + 3*BSTG_NT)*2)   /* 92160 B */
#define SMEM_NN ((3*ASTG + 3*BSTG_NN)*2)   /* 81408 B */

// ---------------- static device scratch ----------------
__device__ bf16  g_Wproj[(size_t)HID*HID];
__device__ bf16  g_Wqkv [(size_t)HID*QKVW];
__device__ bf16  g_W0   [(size_t)HID*HID];
__device__ bf16  g_pe   [(size_t)SQ*HID];       // sinusoidal PE matrix (bf16)
__device__ bf16  g_W2   [(size_t)HID*QKVW];     // Wproj @ Wqkv
__device__ bf16  g_peqkv[(size_t)SQ*QKVW];      // PE @ Wqkv
__device__ bf16  g_Eb   [(size_t)4*VOCP*128];   // padded bf16 embedding tables
__device__ bf16  g_T    [(size_t)4*VOCP*QKVW];  // T_f = E_f @ W2_f  (25 MB)
__device__ bf16  g_Wsm  [(size_t)4*QKVW];       // Wc @ W2[512:1024]
__device__ bf16  g_qkvb [(size_t)TOK*QKVW];
__device__ bf16  g_p    [(size_t)NB*SQ*SQ];     // bf16 scores, softmaxed in place
__device__ bf16  g_zb   [(size_t)TOK*HID];
__device__ bf16  g_hb   [(size_t)TOK*HID];

// ---------------- helpers ----------------
__device__ __forceinline__ void cpa16(uint32_t s, const void* g){
    asm volatile("cp.async.cg.shared.global [%0], [%1], 16;\n" :: "r"(s), "l"(g));
}
__device__ __forceinline__ void cpa_commit(){
    asm volatile("cp.async.commit_group;\n" ::);
}
__device__ __forceinline__ uint32_t packbf(float a, float b){
    float2 f; f.x = a; f.y = b;
    __nv_bfloat162 t = __float22bfloat162_rn(f);
    return *reinterpret_cast<uint32_t*>(&t);
}
__device__ __forceinline__ void addbf8(float* a, uint4 u){
    float2 x0 = __bfloat1622float2(*(const __nv_bfloat162*)&u.x);
    float2 x1 = __bfloat1622float2(*(const __nv_bfloat162*)&u.y);
    float2 x2 = __bfloat1622float2(*(const __nv_bfloat162*)&u.z);
    float2 x3 = __bfloat1622float2(*(const __nv_bfloat162*)&u.w);
    a[0]+=x0.x; a[1]+=x0.y; a[2]+=x1.x; a[3]+=x1.y;
    a[4]+=x2.x; a[5]+=x2.y; a[6]+=x3.x; a[7]+=x3.y;
}
__device__ __forceinline__ void fmabf8(float* a, uint4 u, float c){
    float2 x0 = __bfloat1622float2(*(const __nv_bfloat162*)&u.x);
    float2 x1 = __bfloat1622float2(*(const __nv_bfloat162*)&u.y);
    float2 x2 = __bfloat1622float2(*(const __nv_bfloat162*)&u.z);
    float2 x3 = __bfloat1622float2(*(const __nv_bfloat162*)&u.w);
    a[0]+=c*x0.x; a[1]+=c*x0.y; a[2]+=c*x1.x; a[3]+=c*x1.y;
    a[4]+=c*x2.x; a[5]+=c*x2.y; a[6]+=c*x3.x; a[7]+=c*x3.y;
}

enum { EPI_BF16 = 0 };

// ---------------- pipelined wmma GEMM: C[M,N] = A[M,K] * (BT ? B^T : B) -------
template<bool BT, int EPI>
__global__ void __launch_bounds__(256, 1) gemm2(
    const bf16* __restrict__ A, const bf16* __restrict__ B, void* __restrict__ Cp,
    int K, int lda, int ldb, int ldc, int aYs, int bYs)
{
    extern __shared__ bf16 sm[];
    bf16* sA = sm;
    bf16* sB = sm + 3*ASTG;
    const int BSTG = BT ? BSTG_NT : BSTG_NN;

    const int tid  = threadIdx.x;
    const int warp = tid >> 5, lane = tid & 31;
    const int n0   = blockIdx.x * BN;
    const int row0 = blockIdx.y * BM;
    const int bz   = blockIdx.z;
    const int ay   = bz*aYs + row0;
    const int by   = bz*bYs + (BT ? n0 : 0);
    const int kt   = K / BK;
    const int wm   = warp >> 2, wn = warp & 3;     // 2x4 warp grid, 64x64 each

    wmma::fragment<wmma::accumulator,16,16,16,float> acc[4][4];
    #pragma unroll
    for (int i = 0; i < 4; i++)
        #pragma unroll
        for (int j = 0; j < 4; j++)
            wmma::fill_fragment(acc[i][j], 0.0f);

    auto issue = [&](int k, int st){
        uint32_t sa = (uint32_t)__cvta_generic_to_shared(sA + st*ASTG);
        #pragma unroll
        for (int i = 0; i < 2; i++) {
            int idx = tid + i*256, r = idx >> 2, c = (idx & 3) * 8;
            cpa16(sa + (r*ASTRIDE + c)*2, A + (size_t)(ay + r)*lda + k*BK + c);
        }
        uint32_t sb = (uint32_t)__cvta_generic_to_shared(sB + st*BSTG);
        if (BT) {
            #pragma unroll
            for (int i = 0; i < 4; i++) {
                int idx = tid + i*256, r = idx >> 2, c = (idx & 3) * 8;
                cpa16(sb + (r*ASTRIDE + c)*2, B + (size_t)(by + r)*ldb + k*BK + c);
            }
        } else {
            #pragma unroll
            for (int i = 0; i < 4; i++) {
                int idx = tid + i*256, r = idx >> 5, c = (idx & 31) * 8;
                cpa16(sb + (r*BSTRIDE_NN + c)*2, B + (size_t)(by + k*BK + r)*ldb + n0 + c);
            }
        }
        cpa_commit();
    };

    issue(0, 0);
    issue(1, 1);

    for (int k = 0; k < kt; k++) {
        if (k < kt - 1) asm volatile("cp.async.wait_group 1;\n" ::);
        else            asm volatile("cp.async.wait_group 0;\n" ::);
        __syncthreads();
        if (k + 2 < kt) issue(k + 2, (k + 2) % 3);

        const bf16* a0 = sA + (k % 3)*ASTG;
        const bf16* b0 = sB + (k % 3)*BSTG;

        #pragma unroll
        for (int kk = 0; kk < BK; kk += 16) {
            wmma::fragment<wmma::matrix_a,16,16,16,bf16,wmma::row_major> af[4];
            #pragma unroll
            for (int i = 0; i < 4; i++)
                wmma::load_matrix_sync(af[i], a0 + (wm*64 + i*16)*ASTRIDE + kk, ASTRIDE);
            if (BT) {
                #pragma unroll
                for (int j = 0; j < 4; j++) {
                    wmma::fragment<wmma::matrix_b,16,16,16,bf16,wmma::col_major> bfr;
                    wmma::load_matrix_sync(bfr, b0 + (wn*64 + j*16)*ASTRIDE + kk, ASTRIDE);
                    #pragma unroll
                    for (int i = 0; i < 4; i++)
                        wmma::mma_sync(acc[i][j], af[i], bfr, acc[i][j]);
                }
            } else {
                #pragma unroll
                for (int j = 0; j < 4; j++) {
                    wmma::fragment<wmma::matrix_b,16,16,16,bf16,wmma::row_major> bfr;
                    wmma::load_matrix_sync(bfr, b0 + kk*BSTRIDE_NN + wn*64 + j*16, BSTRIDE_NN);
                    #pragma unroll
                    for (int i = 0; i < 4; i++)
                        wmma::mma_sync(acc[i][j], af[i], bfr, acc[i][j]);
                }
            }
        }
    }
    __syncthreads();   // all cp.async drained; smem reusable as epilogue scratch

    // ---- epilogue: stage frags through smem, emit bf16 ----
    float* scr = (float*)sm + warp*336;   // 16x20 f32 per-warp scratch
    const int r = lane >> 1, hf = lane & 1;
    #pragma unroll
    for (int i = 0; i < 4; i++) {
        const int grow = ay + wm*64 + i*16 + r;
        #pragma unroll
        for (int j = 0; j < 4; j++) {
            wmma::store_matrix_sync(scr, acc[i][j], 20, wmma::mem_row_major);
            __syncwarp();
            const float* sp = scr + r*20 + hf*8;
            const int gcol = n0 + wn*64 + j*16 + hf*8;
            float4 v0 = reinterpret_cast<const float4*>(sp)[0];
            float4 v1 = reinterpret_cast<const float4*>(sp)[1];
            uint4 u;
            u.x = packbf(v0.x, v0.y); u.y = packbf(v0.z, v0.w);
            u.z = packbf(v1.x, v1.y); u.w = packbf(v1.z, v1.w);
            *reinterpret_cast<uint4*>((bf16*)Cp + (size_t)grow*ldc + gcol) = u;
            __syncwarp();
        }
    }
}

// ---------------- weight prep ----------------
__global__ void convert_kernel(const float* __restrict__ in, bf16* __restrict__ out, size_t n)
{
    size_t i = (size_t)blockIdx.x * blockDim.x + threadIdx.x;
    size_t stride = (size_t)gridDim.x * blockDim.x;
    for (; i < n; i += stride) out[i] = __float2bfloat16(in[i]);
}

__global__ void pack_qkv_kernel(const float* __restrict__ q1, const float* __restrict__ k1,
                                const float* __restrict__ v1, const float* __restrict__ q2,
                                const float* __restrict__ k2, const float* __restrict__ v2)
{
    int idx = blockIdx.x * blockDim.x + threadIdx.x;
    if (idx >= HID * QKVW) return;
    int h = idx / QKVW, j = idx % QKVW;
    int sel = j >> 9, jj = j & 511;
    const float* srcs[6] = {q1, k1, v1, q2, k2, v2};
    g_Wqkv[idx] = __float2bfloat16(srcs[sel][h*512 + jj]);
}

// ---- padded bf16 embedding tables: g_Eb[f][0:1000] = E_f, rows 1000+ = 0 ----
__global__ void pad_emb_kernel(const float* __restrict__ E0, const float* __restrict__ E1,
                               const float* __restrict__ E2, const float* __restrict__ E3)
{
    int idx = blockIdx.x * blockDim.x + threadIdx.x;   // 4*VOCP*128 threads
    if (idx >= 4*VOCP*128) return;
    int f = idx / (VOCP*128);
    int rc = idx % (VOCP*128);
    int row = rc >> 7;
    const float* E = (f == 0) ? E0 : (f == 1) ? E1 : (f == 2) ? E2 : E3;
    g_Eb[idx] = (row < VOC) ? __float2bfloat16(E[(size_t)row*128 + (rc & 127)])
                            : __float2bfloat16(0.0f);
}

// ---- Wsmall = Wc @ W2[512:1024]  ([4,3072] bf16) ----
__global__ void wsmall_kernel(const float* __restrict__ Wc)
{
    int idx = blockIdx.x * blockDim.x + threadIdx.x;   // 4*QKVW threads
    if (idx >= 4*QKVW) return;
    int c = idx / QKVW, j = idx % QKVW;
    float acc = 0.0f;
    for (int k = 0; k < 512; k++)
        acc += Wc[c*512 + k] * __bfloat162float(g_W2[(size_t)(512 + k)*QKVW + j]);
    g_Wsm[idx] = __float2bfloat16(acc);
}

// ---------------- PE matrix ----------------
__global__ void gen_pe_kernel()
{
    int idx = blockIdx.x * blockDim.x + threadIdx.x;   // SQ*512 threads
    if (idx >= SQ * 512) return;
    int srow = idx >> 9;
    int ii   = idx & 511;
    float freq = expf(-0.017988946039016305f * (float)ii);  // ln(1e4)*2/1024
    float sn, cs;
    sincosf((float)srow * freq, &sn, &cs);
    *reinterpret_cast<uint32_t*>(&g_pe[(size_t)srow * HID + 2*ii]) = packbf(sn, cs);
}

// ---------------- qkv assembly: gather-sum replaces the 103-GMAC GEMM ---------
// qkv[tok] = T0[id0] + T1[id1] + T2[id2] + T3[id3] + Σc cont_c*Wsm[c] + PEQKV[srow]
__global__ void __launch_bounds__(256) qkv_assemble(
    const int* __restrict__ cate, const float* __restrict__ cont)
{
    int idx = blockIdx.x * blockDim.x + threadIdx.x;   // TOK*384 threads, 8 cols each
    int tok = idx / 384;
    int jb  = (idx % 384) * 8;
    int srow = tok & (SQ - 1);

    const int4  id = *reinterpret_cast<const int4*>(&cate[tok*4]);
    const float4 c = *reinterpret_cast<const float4*>(&cont[tok*4]);

    float a[8];
    uint4 u = *reinterpret_cast<const uint4*>(&g_peqkv[(size_t)srow*QKVW + jb]);
    {
        float2 x0 = __bfloat1622float2(*(const __nv_bfloat162*)&u.x);
        float2 x1 = __bfloat1622float2(*(const __nv_bfloat162*)&u.y);
        float2 x2 = __bfloat1622float2(*(const __nv_bfloat162*)&u.z);
        float2 x3 = __bfloat1622float2(*(const __nv_bfloat162*)&u.w);
        a[0]=x0.x; a[1]=x0.y; a[2]=x1.x; a[3]=x1.y;
        a[4]=x2.x; a[5]=x2.y; a[6]=x3.x; a[7]=x3.y;
    }
    addbf8(a, *reinterpret_cast<const uint4*>(&g_T[((size_t)0*VOCP + id.x)*QKVW + jb]));
    addbf8(a, *reinterpret_cast<const uint4*>(&g_T[((size_t)1*VOCP + id.y)*QKVW + jb]));
    addbf8(a, *reinterpret_cast<const uint4*>(&g_T[((size_t)2*VOCP + id.z)*QKVW + jb]));
    addbf8(a, *reinterpret_cast<const uint4*>(&g_T[((size_t)3*VOCP + id.w)*QKVW + jb]));
    fmabf8(a, *reinterpret_cast<const uint4*>(&g_Wsm[0*QKVW + jb]), c.x);
    fmabf8(a, *reinterpret_cast<const uint4*>(&g_Wsm[1*QKVW + jb]), c.y);
    fmabf8(a, *reinterpret_cast<const uint4*>(&g_Wsm[2*QKVW + jb]), c.z);
    fmabf8(a, *reinterpret_cast<const uint4*>(&g_Wsm[3*QKVW + jb]), c.w);

    uint4 o;
    o.x = packbf(a[0], a[1]); o.y = packbf(a[2], a[3]);
    o.z = packbf(a[4], a[5]); o.w = packbf(a[6], a[7]);
    *reinterpret_cast<uint4*>(&g_qkvb[(size_t)tok*QKVW + jb]) = o;
}

// ---------------- softmax over QUERY axis, bf16 in-place (applies scale) ------
__global__ void softmax_kernel(bf16* __restrict__ P)
{
    int k = blockIdx.x * blockDim.x + threadIdx.x;
    bf16* p = P + (size_t)blockIdx.y * SQ * SQ + k;
    const float scale = 0.04419417382415922f;        // 1/sqrt(512)
    float m = -1e30f, l = 0.0f;
    for (int q = 0; q < SQ; q++) {
        float v = __bfloat162float(p[(size_t)q * SQ]) * scale;
        if (v > m) { l = l * __expf(m - v); m = v; }
        l += __expf(v - m);
    }
    float inv = 1.0f / l;
    for (int q = 0; q < SQ; q++) {
        float v = __bfloat162float(p[(size_t)q * SQ]) * scale;
        p[(size_t)q * SQ] = __float2bfloat16(__expf(v - m) * inv);
    }
}

// ---------------- final: out = sigmoid(h @ Wf), one warp per row --------------
__global__ void final_kernel(const float* __restrict__ Wf, float* __restrict__ out)
{
    int gid  = blockIdx.x * blockDim.x + threadIdx.x;
    int row  = gid >> 5;
    int lane = gid & 31;
    const bf16* h = g_hb + (size_t)row * HID;
    float acc = 0.0f;
    for (int j = lane; j < HID; j += 32) acc += __bfloat162float(h[j]) * Wf[j];
    #pragma unroll
    for (int o = 16; o; o >>= 1) acc += __shfl_xor_sync(0xffffffffu, acc, o);
    if (lane == 0) out[row] = 1.0f / (1.0f + __expf(-acc));
}

// ==============================================================================
extern "C" void kernel_launch(void* const* d_in, const int* in_sizes, int n_in,
                              void* d_out, int out_size)
{
    const int*   cate  = (const int*)  d_in[0];
    const float* cont  = (const float*)d_in[1];
    const float* E0    = (const float*)d_in[4];
    const float* E1    = (const float*)d_in[5];
    const float* E2    = (const float*)d_in[6];
    const float* E3    = (const float*)d_in[7];
    const float* Wc    = (const float*)d_in[8];
    const float* Wproj = (const float*)d_in[9];
    const float* WQ1   = (const float*)d_in[10];
    const float* WK1   = (const float*)d_in[11];
    const float* WV1   = (const float*)d_in[12];
    const float* WQ2   = (const float*)d_in[13];
    const float* WK2   = (const float*)d_in[14];
    const float* WV2   = (const float*)d_in[15];
    const float* W0    = (const float*)d_in[16];
    const float* Wf    = (const float*)d_in[17];
    float* out = (float*)d_out;

    bf16 *Wp, *Wqkv, *W0b, *pe, *W2, *peqkv, *Eb, *T, *qkvb, *p, *zb, *hb;
    cudaGetSymbolAddress((void**)&Wp,    g_Wproj);
    cudaGetSymbolAddress((void**)&Wqkv,  g_Wqkv);
    cudaGetSymbolAddress((void**)&W0b,   g_W0);
    cudaGetSymbolAddress((void**)&pe,    g_pe);
    cudaGetSymbolAddress((void**)&W2,    g_W2);
    cudaGetSymbolAddress((void**)&peqkv, g_peqkv);
    cudaGetSymbolAddress((void**)&Eb,    g_Eb);
    cudaGetSymbolAddress((void**)&T,     g_T);
    cudaGetSymbolAddress((void**)&qkvb,  g_qkvb);
    cudaGetSymbolAddress((void**)&p,     g_p);
    cudaGetSymbolAddress((void**)&zb,    g_zb);
    cudaGetSymbolAddress((void**)&hb,    g_hb);

    cudaFuncSetAttribute(gemm2<false, EPI_BF16>,
                         cudaFuncAttributeMaxDynamicSharedMemorySize, SMEM_NN);
    cudaFuncSetAttribute(gemm2<true,  EPI_BF16>,
                         cudaFuncAttributeMaxDynamicSharedMemorySize, SMEM_NT);

    // ---- weight prep ----
    convert_kernel<<<2048, 256>>>(Wproj, Wp,  (size_t)HID*HID);
    convert_kernel<<<2048, 256>>>(W0,    W0b, (size_t)HID*HID);
    pack_qkv_kernel<<<(HID*QKVW + 255)/256, 256>>>(WQ1, WK1, WV1, WQ2, WK2, WV2);
    gen_pe_kernel<<<(SQ*512 + 255)/256, 256>>>();
    pad_emb_kernel<<<(4*VOCP*128 + 255)/256, 256>>>(E0, E1, E2, E3);

    // ---- fused weights: W2 = Wproj @ Wqkv ; PEQKV = PE @ Wqkv ----
    gemm2<false, EPI_BF16><<<dim3(QKVW/BN, HID/BM, 1), 256, SMEM_NN>>>(
        Wp, Wqkv, W2, HID, HID, QKVW, QKVW, 0, 0);
    gemm2<false, EPI_BF16><<<dim3(QKVW/BN, SQ/BM, 1), 256, SMEM_NN>>>(
        pe, Wqkv, peqkv, HID, HID, QKVW, QKVW, 0, 0);

    // ---- per-feature qkv tables: T_f = E_f_padded @ W2[f*128:(f+1)*128] ----
    for (int f = 0; f < 4; f++)
        gemm2<false, EPI_BF16><<<dim3(QKVW/BN, VOCP/BM, 1), 256, SMEM_NN>>>(
            Eb + (size_t)f*VOCP*128, W2 + (size_t)f*128*QKVW,
            T + (size_t)f*VOCP*QKVW, 128, 128, QKVW, QKVW, 0, 0);

    // ---- Wsmall = Wc @ W2[512:1024] ----
    wsmall_kernel<<<(4*QKVW + 255)/256, 256>>>(Wc);

    // ---- qkv via gather-sum (the 103-GMAC GEMM is gone) ----
    qkv_assemble<<<TOK*384/256, 256>>>(cate, cont);

    // ---- two attention heads ----
    for (int h = 0; h < 2; h++) {
        const bf16* Qh = qkvb + h*1536;
        const bf16* Kh = qkvb + h*1536 + 512;
        const bf16* Vh = qkvb + h*1536 + 1024;
        gemm2<true, EPI_BF16><<<dim3(SQ/BN, SQ/BM, NB), 256, SMEM_NT>>>(
            Qh, Kh, p, ATT, QKVW, QKVW, SQ, SQ, SQ);
        softmax_kernel<<<dim3(SQ/256, NB), 256>>>(p);
        gemm2<false, EPI_BF16><<<dim3(ATT/BN, SQ/BM, NB), 256, SMEM_NN>>>(
            p, Vh, zb + h*512, SQ, SQ, QKVW, HID, SQ, SQ);
    }

    // ---- h = z @ W0, bf16 out ----
    gemm2<false, EPI_BF16><<<dim3(HID/BN, TOK/BM, 1), 256, SMEM_NN>>>(
        zb, W0b, hb, HID, HID, HID, HID, 0, 0);

    // ---- out = sigmoid(h @ Wf) ----
    final_kernel<<<TOK/8, 256>>>(Wf, out);
}

// round 17
// speedup vs baseline: 2.2945x; 1.0462x over previous
#include <cuda_runtime.h>
#include <cuda_bf16.h>
#include <mma.h>
#include <math.h>
#include <stdint.h>

using namespace nvcuda;
typedef __nv_bfloat16 bf16;

#define NB   32
#define SQ   1024
#define HID  1024
#define ATT  512
#define TOK  (NB*SQ)          /* 32768 */
#define QKVW 3072
#define VOC  1000
#define VOCP 1024             /* padded vocab rows */

// GEMM tiling: 128x256 CTA tile, 512 threads (16 warps at 64x32 each)
#define BM 128
#define BN 256
#define BK 32
#define NTHR 512
#define ASTRIDE 40            /* 32 + 8 pad, elements */
#define BSTRIDE_NN 264        /* 256 + 8 pad */
#define ASTG (BM*ASTRIDE)               /* 5120 elem  */
#define BSTG_NT (BN*ASTRIDE)            /* 10240 elem */
#define BSTG_NN (BK*BSTRIDE_NN)         /* 8448 elem  */
#define SMEM_NT ((3*ASTG + 3*BSTG_NT)*2)   /* 92160 B */
#define SMEM_NN ((3*ASTG + 3*BSTG_NN)*2)   /* 81408 B */

// ---------------- static device scratch ----------------
__device__ bf16  g_Wproj[(size_t)HID*HID];
__device__ bf16  g_Wqkv [(size_t)HID*QKVW];
__device__ bf16  g_pe   [(size_t)SQ*HID];       // sinusoidal PE matrix (bf16)
__device__ bf16  g_W2   [(size_t)HID*QKVW];     // Wproj @ Wqkv
__device__ bf16  g_peqkv[(size_t)SQ*QKVW];      // PE @ Wqkv
__device__ bf16  g_Eb   [(size_t)4*VOCP*128];   // padded bf16 embedding tables
__device__ bf16  g_T    [(size_t)4*VOCP*QKVW];  // T_f = E_f @ W2_f  (25 MB)
__device__ bf16  g_Wsm  [(size_t)4*QKVW];       // Wc @ W2[512:1024]
__device__ float g_wsf  [HID];                  // W0 @ Wf  (W0 GEMM folded away)
__device__ bf16  g_qkvb [(size_t)TOK*QKVW];
__device__ bf16  g_p    [(size_t)NB*SQ*SQ];     // bf16 scores, softmaxed in place
__device__ bf16  g_zb   [(size_t)TOK*HID];

// ---------------- helpers ----------------
__device__ __forceinline__ void cpa16(uint32_t s, const void* g){
    asm volatile("cp.async.cg.shared.global [%0], [%1], 16;\n" :: "r"(s), "l"(g));
}
__device__ __forceinline__ void cpa_commit(){
    asm volatile("cp.async.commit_group;\n" ::);
}
__device__ __forceinline__ uint32_t packbf(float a, float b){
    float2 f; f.x = a; f.y = b;
    __nv_bfloat162 t = __float22bfloat162_rn(f);
    return *reinterpret_cast<uint32_t*>(&t);
}
__device__ __forceinline__ void addbf8(float* a, uint4 u){
    float2 x0 = __bfloat1622float2(*(const __nv_bfloat162*)&u.x);
    float2 x1 = __bfloat1622float2(*(const __nv_bfloat162*)&u.y);
    float2 x2 = __bfloat1622float2(*(const __nv_bfloat162*)&u.z);
    float2 x3 = __bfloat1622float2(*(const __nv_bfloat162*)&u.w);
    a[0]+=x0.x; a[1]+=x0.y; a[2]+=x1.x; a[3]+=x1.y;
    a[4]+=x2.x; a[5]+=x2.y; a[6]+=x3.x; a[7]+=x3.y;
}
__device__ __forceinline__ void fmabf8(float* a, uint4 u, float c){
    float2 x0 = __bfloat1622float2(*(const __nv_bfloat162*)&u.x);
    float2 x1 = __bfloat1622float2(*(const __nv_bfloat162*)&u.y);
    float2 x2 = __bfloat1622float2(*(const __nv_bfloat162*)&u.z);
    float2 x3 = __bfloat1622float2(*(const __nv_bfloat162*)&u.w);
    a[0]+=c*x0.x; a[1]+=c*x0.y; a[2]+=c*x1.x; a[3]+=c*x1.y;
    a[4]+=c*x2.x; a[5]+=c*x2.y; a[6]+=c*x3.x; a[7]+=c*x3.y;
}

enum { EPI_BF16 = 0 };

// ---------------- pipelined wmma GEMM: C[M,N] = A[M,K] * (BT ? B^T : B) -------
// 512 threads, 16 warps as 2(M)x8(N), 64x32 warp tile, acc 4x2.
template<bool BT, int EPI>
__global__ void __launch_bounds__(NTHR, 1) gemm2(
    const bf16* __restrict__ A, const bf16* __restrict__ B, void* __restrict__ Cp,
    int K, int lda, int ldb, int ldc, int aYs, int bYs)
{
    extern __shared__ bf16 sm[];
    bf16* sA = sm;
    bf16* sB = sm + 3*ASTG;
    const int BSTG = BT ? BSTG_NT : BSTG_NN;

    const int tid  = threadIdx.x;
    const int warp = tid >> 5, lane = tid & 31;
    const int n0   = blockIdx.x * BN;
    const int row0 = blockIdx.y * BM;
    const int bz   = blockIdx.z;
    const int ay   = bz*aYs + row0;
    const int by   = bz*bYs + (BT ? n0 : 0);
    const int kt   = K / BK;
    const int wm   = warp >> 3, wn = warp & 7;     // 2x8 warp grid, 64x32 each

    wmma::fragment<wmma::accumulator,16,16,16,float> acc[4][2];
    #pragma unroll
    for (int i = 0; i < 4; i++)
        #pragma unroll
        for (int j = 0; j < 2; j++)
            wmma::fill_fragment(acc[i][j], 0.0f);

    auto issue = [&](int k, int st){
        uint32_t sa = (uint32_t)__cvta_generic_to_shared(sA + st*ASTG);
        {   // A tile 128x32: 512 x 16B = exactly one load per thread
            int r = tid >> 2, c = (tid & 3) * 8;
            cpa16(sa + (r*ASTRIDE + c)*2, A + (size_t)(ay + r)*lda + k*BK + c);
        }
        uint32_t sb = (uint32_t)__cvta_generic_to_shared(sB + st*BSTG);
        if (BT) {
            #pragma unroll
            for (int i = 0; i < 2; i++) {
                int idx = tid + i*NTHR, r = idx >> 2, c = (idx & 3) * 8;
                cpa16(sb + (r*ASTRIDE + c)*2, B + (size_t)(by + r)*ldb + k*BK + c);
            }
        } else {
            #pragma unroll
            for (int i = 0; i < 2; i++) {
                int idx = tid + i*NTHR, r = idx >> 5, c = (idx & 31) * 8;
                cpa16(sb + (r*BSTRIDE_NN + c)*2, B + (size_t)(by + k*BK + r)*ldb + n0 + c);
            }
        }
        cpa_commit();
    };

    issue(0, 0);
    issue(1, 1);

    for (int k = 0; k < kt; k++) {
        if (k < kt - 1) asm volatile("cp.async.wait_group 1;\n" ::);
        else            asm volatile("cp.async.wait_group 0;\n" ::);
        __syncthreads();
        if (k + 2 < kt) issue(k + 2, (k + 2) % 3);

        const bf16* a0 = sA + (k % 3)*ASTG;
        const bf16* b0 = sB + (k % 3)*BSTG;

        #pragma unroll
        for (int kk = 0; kk < BK; kk += 16) {
            wmma::fragment<wmma::matrix_a,16,16,16,bf16,wmma::row_major> af[4];
            #pragma unroll
            for (int i = 0; i < 4; i++)
                wmma::load_matrix_sync(af[i], a0 + (wm*64 + i*16)*ASTRIDE + kk, ASTRIDE);
            if (BT) {
                #pragma unroll
                for (int j = 0; j < 2; j++) {
                    wmma::fragment<wmma::matrix_b,16,16,16,bf16,wmma::col_major> bfr;
                    wmma::load_matrix_sync(bfr, b0 + (wn*32 + j*16)*ASTRIDE + kk, ASTRIDE);
                    #pragma unroll
                    for (int i = 0; i < 4; i++)
                        wmma::mma_sync(acc[i][j], af[i], bfr, acc[i][j]);
                }
            } else {
                #pragma unroll
                for (int j = 0; j < 2; j++) {
                    wmma::fragment<wmma::matrix_b,16,16,16,bf16,wmma::row_major> bfr;
                    wmma::load_matrix_sync(bfr, b0 + kk*BSTRIDE_NN + wn*32 + j*16, BSTRIDE_NN);
                    #pragma unroll
                    for (int i = 0; i < 4; i++)
                        wmma::mma_sync(acc[i][j], af[i], bfr, acc[i][j]);
                }
            }
        }
    }
    __syncthreads();   // all cp.async drained; smem reusable as epilogue scratch

    // ---- epilogue: stage frags through smem, emit bf16 ----
    float* scr = (float*)sm + warp*336;   // 16x20 f32 per-warp scratch (16 warps: 21.5KB)
    const int r = lane >> 1, hf = lane & 1;
    #pragma unroll
    for (int i = 0; i < 4; i++) {
        const int grow = ay + wm*64 + i*16 + r;
        #pragma unroll
        for (int j = 0; j < 2; j++) {
            wmma::store_matrix_sync(scr, acc[i][j], 20, wmma::mem_row_major);
            __syncwarp();
            const float* sp = scr + r*20 + hf*8;
            const int gcol = n0 + wn*32 + j*16 + hf*8;
            float4 v0 = reinterpret_cast<const float4*>(sp)[0];
            float4 v1 = reinterpret_cast<const float4*>(sp)[1];
            uint4 u;
            u.x = packbf(v0.x, v0.y); u.y = packbf(v0.z, v0.w);
            u.z = packbf(v1.x, v1.y); u.w = packbf(v1.z, v1.w);
            *reinterpret_cast<uint4*>((bf16*)Cp + (size_t)grow*ldc + gcol) = u;
            __syncwarp();
        }
    }
}

// ---------------- weight prep ----------------
__global__ void convert_kernel(const float* __restrict__ in, bf16* __restrict__ out, size_t n)
{
    size_t i = (size_t)blockIdx.x * blockDim.x + threadIdx.x;
    size_t stride = (size_t)gridDim.x * blockDim.x;
    for (; i < n; i += stride) out[i] = __float2bfloat16(in[i]);
}

__global__ void pack_qkv_kernel(const float* __restrict__ q1, const float* __restrict__ k1,
                                const float* __restrict__ v1, const float* __restrict__ q2,
                                const float* __restrict__ k2, const float* __restrict__ v2)
{
    int idx = blockIdx.x * blockDim.x + threadIdx.x;
    if (idx >= HID * QKVW) return;
    int h = idx / QKVW, j = idx % QKVW;
    int sel = j >> 9, jj = j & 511;
    const float* srcs[6] = {q1, k1, v1, q2, k2, v2};
    g_Wqkv[idx] = __float2bfloat16(srcs[sel][h*512 + jj]);
}

__global__ void pad_emb_kernel(const float* __restrict__ E0, const float* __restrict__ E1,
                               const float* __restrict__ E2, const float* __restrict__ E3)
{
    int idx = blockIdx.x * blockDim.x + threadIdx.x;   // 4*VOCP*128 threads
    if (idx >= 4*VOCP*128) return;
    int f = idx / (VOCP*128);
    int rc = idx % (VOCP*128);
    int row = rc >> 7;
    const float* E = (f == 0) ? E0 : (f == 1) ? E1 : (f == 2) ? E2 : E3;
    g_Eb[idx] = (row < VOC) ? __float2bfloat16(E[(size_t)row*128 + (rc & 127)])
                            : __float2bfloat16(0.0f);
}

// ---- Wsmall = Wc @ W2[512:1024]  ([4,3072] bf16) ----
__global__ void wsmall_kernel(const float* __restrict__ Wc)
{
    int idx = blockIdx.x * blockDim.x + threadIdx.x;   // 4*QKVW threads
    if (idx >= 4*QKVW) return;
    int c = idx / QKVW, j = idx % QKVW;
    float acc = 0.0f;
    for (int k = 0; k < 512; k++)
        acc += Wc[c*512 + k] * __bfloat162float(g_W2[(size_t)(512 + k)*QKVW + j]);
    g_Wsm[idx] = __float2bfloat16(acc);
}

// ---- wsf = W0 @ Wf  (f32 [1024]; folds the whole W0 GEMM into final matvec) ----
__global__ void w0wf_kernel(const float* __restrict__ W0, const float* __restrict__ Wf)
{
    int gid = blockIdx.x * blockDim.x + threadIdx.x;   // HID*32 threads
    int row = gid >> 5, lane = gid & 31;
    if (row >= HID) return;
    float acc = 0.0f;
    for (int j = lane; j < HID; j += 32) acc += W0[(size_t)row*HID + j] * Wf[j];
    #pragma unroll
    for (int o = 16; o; o >>= 1) acc += __shfl_xor_sync(0xffffffffu, acc, o);
    if (lane == 0) g_wsf[row] = acc;
}

// ---------------- PE matrix ----------------
__global__ void gen_pe_kernel()
{
    int idx = blockIdx.x * blockDim.x + threadIdx.x;   // SQ*512 threads
    if (idx >= SQ * 512) return;
    int srow = idx >> 9;
    int ii   = idx & 511;
    float freq = expf(-0.017988946039016305f * (float)ii);  // ln(1e4)*2/1024
    float sn, cs;
    sincosf((float)srow * freq, &sn, &cs);
    *reinterpret_cast<uint32_t*>(&g_pe[(size_t)srow * HID + 2*ii]) = packbf(sn, cs);
}

// ---------------- qkv assembly: gather-sum replaces the 103-GMAC GEMM ---------
__global__ void __launch_bounds__(256) qkv_assemble(
    const int* __restrict__ cate, const float* __restrict__ cont)
{
    int idx = blockIdx.x * blockDim.x + threadIdx.x;   // TOK*384 threads, 8 cols each
    int tok = idx / 384;
    int jb  = (idx % 384) * 8;
    int srow = tok & (SQ - 1);

    const int4  id = *reinterpret_cast<const int4*>(&cate[tok*4]);
    const float4 c = *reinterpret_cast<const float4*>(&cont[tok*4]);

    float a[8];
    uint4 u = *reinterpret_cast<const uint4*>(&g_peqkv[(size_t)srow*QKVW + jb]);
    {
        float2 x0 = __bfloat1622float2(*(const __nv_bfloat162*)&u.x);
        float2 x1 = __bfloat1622float2(*(const __nv_bfloat162*)&u.y);
        float2 x2 = __bfloat1622float2(*(const __nv_bfloat162*)&u.z);
        float2 x3 = __bfloat1622float2(*(const __nv_bfloat162*)&u.w);
        a[0]=x0.x; a[1]=x0.y; a[2]=x1.x; a[3]=x1.y;
        a[4]=x2.x; a[5]=x2.y; a[6]=x3.x; a[7]=x3.y;
    }
    addbf8(a, *reinterpret_cast<const uint4*>(&g_T[((size_t)0*VOCP + id.x)*QKVW + jb]));
    addbf8(a, *reinterpret_cast<const uint4*>(&g_T[((size_t)1*VOCP + id.y)*QKVW + jb]));
    addbf8(a, *reinterpret_cast<const uint4*>(&g_T[((size_t)2*VOCP + id.z)*QKVW + jb]));
    addbf8(a, *reinterpret_cast<const uint4*>(&g_T[((size_t)3*VOCP + id.w)*QKVW + jb]));
    fmabf8(a, *reinterpret_cast<const uint4*>(&g_Wsm[0*QKVW + jb]), c.x);
    fmabf8(a, *reinterpret_cast<const uint4*>(&g_Wsm[1*QKVW + jb]), c.y);
    fmabf8(a, *reinterpret_cast<const uint4*>(&g_Wsm[2*QKVW + jb]), c.z);
    fmabf8(a, *reinterpret_cast<const uint4*>(&g_Wsm[3*QKVW + jb]), c.w);

    uint4 o;
    o.x = packbf(a[0], a[1]); o.y = packbf(a[2], a[3]);
    o.z = packbf(a[4], a[5]); o.w = packbf(a[6], a[7]);
    *reinterpret_cast<uint4*>(&g_qkvb[(size_t)tok*QKVW + jb]) = o;
}

// ---------------- softmax over QUERY axis, bf16x2 in-place, no-max ------------
// Logits bounded (|s*scale| << 88), so exp without max-shift is safe in f32.
__global__ void softmax_kernel(bf16* __restrict__ P)
{
    int k2 = blockIdx.x * blockDim.x + threadIdx.x;    // column pair 0..511
    __nv_bfloat162* p = reinterpret_cast<__nv_bfloat162*>(
        P + (size_t)blockIdx.y * SQ * SQ) + k2;
    const float scale = 0.04419417382415922f;          // 1/sqrt(512)
    float s0 = 0.0f, s1 = 0.0f;
    #pragma unroll 4
    for (int q = 0; q < SQ; q++) {
        float2 v = __bfloat1622float2(p[q * (SQ/2)]);
        s0 += __expf(v.x * scale);
        s1 += __expf(v.y * scale);
    }
    float i0 = 1.0f / s0, i1 = 1.0f / s1;
    #pragma unroll 4
    for (int q = 0; q < SQ; q++) {
        float2 v = __bfloat1622float2(p[q * (SQ/2)]);
        *reinterpret_cast<uint32_t*>(&p[q * (SQ/2)]) =
            packbf(__expf(v.x * scale) * i0, __expf(v.y * scale) * i1);
    }
}

// ---------------- final: out = sigmoid(z @ wsf), one warp per row -------------
__global__ void final_kernel(float* __restrict__ out)
{
    int gid  = blockIdx.x * blockDim.x + threadIdx.x;
    int row  = gid >> 5;
    int lane = gid & 31;
    const bf16* z = g_zb + (size_t)row * HID;
    float acc = 0.0f;
    for (int j = lane; j < HID; j += 32) acc += __bfloat162float(z[j]) * g_wsf[j];
    #pragma unroll
    for (int o = 16; o; o >>= 1) acc += __shfl_xor_sync(0xffffffffu, acc, o);
    if (lane == 0) out[row] = 1.0f / (1.0f + __expf(-acc));
}

// ==============================================================================
extern "C" void kernel_launch(void* const* d_in, const int* in_sizes, int n_in,
                              void* d_out, int out_size)
{
    const int*   cate  = (const int*)  d_in[0];
    const float* cont  = (const float*)d_in[1];
    const float* E0    = (const float*)d_in[4];
    const float* E1    = (const float*)d_in[5];
    const float* E2    = (const float*)d_in[6];
    const float* E3    = (const float*)d_in[7];
    const float* Wc    = (const float*)d_in[8];
    const float* Wproj = (const float*)d_in[9];
    const float* WQ1   = (const float*)d_in[10];
    const float* WK1   = (const float*)d_in[11];
    const float* WV1   = (const float*)d_in[12];
    const float* WQ2   = (const float*)d_in[13];
    const float* WK2   = (const float*)d_in[14];
    const float* WV2   = (const float*)d_in[15];
    const float* W0    = (const float*)d_in[16];
    const float* Wf    = (const float*)d_in[17];
    float* out = (float*)d_out;

    bf16 *Wp, *Wqkv, *pe, *W2, *peqkv, *Eb, *T, *qkvb, *p, *zb;
    cudaGetSymbolAddress((void**)&Wp,    g_Wproj);
    cudaGetSymbolAddress((void**)&Wqkv,  g_Wqkv);
    cudaGetSymbolAddress((void**)&pe,    g_pe);
    cudaGetSymbolAddress((void**)&W2,    g_W2);
    cudaGetSymbolAddress((void**)&peqkv, g_peqkv);
    cudaGetSymbolAddress((void**)&Eb,    g_Eb);
    cudaGetSymbolAddress((void**)&T,     g_T);
    cudaGetSymbolAddress((void**)&qkvb,  g_qkvb);
    cudaGetSymbolAddress((void**)&p,     g_p);
    cudaGetSymbolAddress((void**)&zb,    g_zb);

    cudaFuncSetAttribute(gemm2<false, EPI_BF16>,
                         cudaFuncAttributeMaxDynamicSharedMemorySize, SMEM_NN);
    cudaFuncSetAttribute(gemm2<true,  EPI_BF16>,
                         cudaFuncAttributeMaxDynamicSharedMemorySize, SMEM_NT);

    // ---- weight prep ----
    convert_kernel<<<2048, 256>>>(Wproj, Wp, (size_t)HID*HID);
    pack_qkv_kernel<<<(HID*QKVW + 255)/256, 256>>>(WQ1, WK1, WV1, WQ2, WK2, WV2);
    gen_pe_kernel<<<(SQ*512 + 255)/256, 256>>>();
    pad_emb_kernel<<<(4*VOCP*128 + 255)/256, 256>>>(E0, E1, E2, E3);
    w0wf_kernel<<<HID*32/256, 256>>>(W0, Wf);

    // ---- fused weights: W2 = Wproj @ Wqkv ; PEQKV = PE @ Wqkv ----
    gemm2<false, EPI_BF16><<<dim3(QKVW/BN, HID/BM, 1), NTHR, SMEM_NN>>>(
        Wp, Wqkv, W2, HID, HID, QKVW, QKVW, 0, 0);
    gemm2<false, EPI_BF16><<<dim3(QKVW/BN, SQ/BM, 1), NTHR, SMEM_NN>>>(
        pe, Wqkv, peqkv, HID, HID, QKVW, QKVW, 0, 0);

    // ---- per-feature qkv tables: T_f = E_f_padded @ W2[f*128:(f+1)*128] ----
    for (int f = 0; f < 4; f++)
        gemm2<false, EPI_BF16><<<dim3(QKVW/BN, VOCP/BM, 1), NTHR, SMEM_NN>>>(
            Eb + (size_t)f*VOCP*128, W2 + (size_t)f*128*QKVW,
            T + (size_t)f*VOCP*QKVW, 128, 128, QKVW, QKVW, 0, 0);

    // ---- Wsmall = Wc @ W2[512:1024] ----
    wsmall_kernel<<<(4*QKVW + 255)/256, 256>>>(Wc);

    // ---- qkv via gather-sum ----
    qkv_assemble<<<TOK*384/256, 256>>>(cate, cont);

    // ---- two attention heads ----
    for (int h = 0; h < 2; h++) {
        const bf16* Qh = qkvb + h*1536;
        const bf16* Kh = qkvb + h*1536 + 512;
        const bf16* Vh = qkvb + h*1536 + 1024;
        gemm2<true, EPI_BF16><<<dim3(SQ/BN, SQ/BM, NB), NTHR, SMEM_NT>>>(
            Qh, Kh, p, ATT, QKVW, QKVW, SQ, SQ, SQ);
        softmax_kernel<<<dim3(SQ/2/256, NB), 256>>>(p);
        gemm2<false, EPI_BF16><<<dim3(ATT/BN, SQ/BM, NB), NTHR, SMEM_NN>>>(
            p, Vh, zb + h*512, SQ, SQ, QKVW, HID, SQ, SQ);
    }

    // ---- out = sigmoid(z @ (W0@Wf))  (W0 GEMM folded into final matvec) ----
    final_kernel<<<TOK*32/256, 256>>>(out);
}